// round 17
// baseline (speedup 1.0000x reference)
#include <cuda_runtime.h>
#include <cuda_fp16.h>
#include <cstdint>

#define N_TOK 4096
#define D_IN  1024
#define D_HID 4096
#define D_OUT 1024
#define N_EXP 8

// ---------------- scratch (device globals; no runtime allocation) ----------------
__device__ __half g_Xh[(size_t)N_TOK * D_IN];            // x in fp16
__device__ __half g_W1h[(size_t)N_EXP * D_IN * D_HID];   // W1 fp16, natural [e][K=1024][N=4096]
__device__ __half g_W2h[(size_t)N_EXP * D_HID * D_OUT];  // W2 fp16, natural [e][K=4096][N=1024]
__device__ __half g_Hh[(size_t)N_TOK * 2 * D_HID];       // hidden acts fp16 per slot (k-major)
__device__ float  g_topk_w[N_TOK * 2];
__device__ int    g_count[N_EXP];
__device__ int    g_slots[N_EXP * N_TOK];                // slot = 2*token + k

// ---------------- helpers ----------------
__device__ __forceinline__ uint32_t s2u(const void* p) {
    return (uint32_t)__cvta_generic_to_shared(p);
}
__device__ __forceinline__ void cpa16(uint32_t d, const void* g) {
    asm volatile("cp.async.cg.shared.global [%0], [%1], 16;\n" :: "r"(d), "l"(g));
}
#define LDSM_X4(r, a) \
    asm("ldmatrix.sync.aligned.m8n8.x4.shared.b16 {%0,%1,%2,%3}, [%4];" \
        : "=r"((r)[0]), "=r"((r)[1]), "=r"((r)[2]), "=r"((r)[3]) : "r"(a) : "memory")
// transposed variant: fragments from N-contiguous (row=k, col=n) smem
#define LDSM_X4T(r, a) \
    asm("ldmatrix.sync.aligned.m8n8.x4.trans.shared.b16 {%0,%1,%2,%3}, [%4];" \
        : "=r"((r)[0]), "=r"((r)[1]), "=r"((r)[2]), "=r"((r)[3]) : "r"(a) : "memory")

__device__ __forceinline__ void mma_f16(float* d, const uint32_t* a, const uint32_t* b) {
    asm("mma.sync.aligned.m16n8k16.row.col.f32.f16.f16.f32 "
        "{%0,%1,%2,%3}, {%4,%5,%6,%7}, {%8,%9}, {%0,%1,%2,%3};"
        : "+f"(d[0]), "+f"(d[1]), "+f"(d[2]), "+f"(d[3])
        : "r"(a[0]), "r"(a[1]), "r"(a[2]), "r"(a[3]),
          "r"(b[0]), "r"(b[1]));
}
__device__ __forceinline__ void redadd(float* p, float v) {
    asm volatile("red.global.add.f32 [%0], %1;" :: "l"(p), "f"(v) : "memory");
}

// ---------------- init0: zero expert counters (must precede gating atomics) ----------------
__global__ void init0_kernel() {
    if (threadIdx.x < N_EXP) g_count[threadIdx.x] = 0;
}

// ---------------- straight fp32 -> fp16 convert of 2048 float4 (device body) ----------------
__device__ __forceinline__ void convert_block(const float* __restrict__ src,
                                              __half* __restrict__ dst,
                                              size_t base4, int nIter, int nThr, int tid) {
    const float4* s = (const float4*)src + base4;
    half2* d = (half2*)dst + base4 * 2;
    for (int q = 0; q < nIter; q++) {
        size_t i = (size_t)q * nThr + tid;
        float4 v = s[i];
        d[2 * i]     = __floats2half2_rn(v.x, v.y);
        d[2 * i + 1] = __floats2half2_rn(v.z, v.w);
    }
}

// ---------------- P1: fused convert-W1 + gating(+x->fp16) ----------------
// grid: [0,4096) convert W1 (2048 float4 each), [4096,4608) gating (8 tokens each)
__global__ void __launch_bounds__(256)
prep_kernel(const float* __restrict__ x,  const float* __restrict__ W1,
            const float* __restrict__ Wg, const float* __restrict__ bg) {
    const int bid = blockIdx.x;
    const int tid = threadIdx.x;

    if (bid < 4096) {                       // ---- convert W1 (8M float4 total) ----
        convert_block(W1, g_W1h, (size_t)bid * 2048, 8, 256, tid);
        return;
    }

    // ---- gating + x->fp16 for 8 tokens ----
    const int tb   = (bid - 4096) * 8;
    const int tok  = tb + (tid >> 5);
    const int lane = tid & 31;
    {
        const float4* xv = (const float4*)(x + (size_t)tb * D_IN);
        half2* xo = (half2*)(g_Xh + (size_t)tb * D_IN);
#pragma unroll
        for (int i = tid; i < 8 * D_IN / 4; i += 256) {
            float4 v = xv[i];
            xo[2 * i]     = __floats2half2_rn(v.x, v.y);
            xo[2 * i + 1] = __floats2half2_rn(v.z, v.w);
        }
    }

    float acc[8];
#pragma unroll
    for (int e = 0; e < 8; e++) acc[e] = 0.f;
    const float* xr = x + (size_t)tok * D_IN;
    for (int d = lane; d < D_IN; d += 32) {
        float xv = xr[d];
        float4 w0 = *(const float4*)(Wg + d * 8);
        float4 w1 = *(const float4*)(Wg + d * 8 + 4);
        acc[0] += xv * w0.x; acc[1] += xv * w0.y;
        acc[2] += xv * w0.z; acc[3] += xv * w0.w;
        acc[4] += xv * w1.x; acc[5] += xv * w1.y;
        acc[6] += xv * w1.z; acc[7] += xv * w1.w;
    }
#pragma unroll
    for (int off = 16; off > 0; off >>= 1)
#pragma unroll
        for (int e = 0; e < 8; e++)
            acc[e] += __shfl_xor_sync(0xFFFFFFFFu, acc[e], off);

    if (lane == 0) {
        float l[8];
#pragma unroll
        for (int e = 0; e < 8; e++) l[e] = acc[e] + bg[e];
        float mx = l[0];
#pragma unroll
        for (int e = 1; e < 8; e++) mx = fmaxf(mx, l[e]);
        float p[8], s = 0.f;
#pragma unroll
        for (int e = 0; e < 8; e++) { p[e] = expf(l[e] - mx); s += p[e]; }
        float inv = 1.f / s;
#pragma unroll
        for (int e = 0; e < 8; e++) p[e] *= inv;

        int i0 = 0; float v0 = p[0];
#pragma unroll
        for (int e = 1; e < 8; e++) if (p[e] > v0) { v0 = p[e]; i0 = e; }
        int i1 = -1; float v1 = -1.f;
#pragma unroll
        for (int e = 0; e < 8; e++) if (e != i0 && p[e] > v1) { v1 = p[e]; i1 = e; }

        float e1 = expf(v1 - v0);
        float den = 1.f / (1.f + e1);
        int p0 = atomicAdd(&g_count[i0], 1);
        g_slots[i0 * N_TOK + p0] = 2 * tok;
        int p1 = atomicAdd(&g_count[i1], 1);
        g_slots[i1 * N_TOK + p1] = 2 * tok + 1;
        g_topk_w[2 * tok]     = den;
        g_topk_w[2 * tok + 1] = e1 * den;
    }
}

// ---------------- ffn GEMM body: 128x128x64 tile, 3-stage ring, spread cp.async,
// ---------------- A from K-major smem (plain LDSM), B from N-contiguous smem (LDSM.trans)
template <bool FIRST>
__device__ __forceinline__ void ffn_body(int e, int m0, int n0,
                                         const float* __restrict__ Bias,
                                         float* __restrict__ out, char* smem) {
    constexpr int K  = FIRST ? D_IN : D_HID;
    constexpr int N  = FIRST ? D_HID : D_OUT;
    constexpr int BM = 128, BK = 64;
    constexpr int STRA = (BK + 8) * 2;       // A: 144 B/row (128 m-rows x 64 k)
    constexpr int STRBN = 128 * 2 + 16;      // B: 272 B/row (64 k-rows x 128 n), 16B pad
    constexpr int NS = K / BK;
    constexpr int ASTG = BM * STRA;          // 18432 B
    constexpr int BSTG = BK * STRBN;         // 17408 B

    constexpr int OFF_SLOT = 0;
    constexpr int OFF_A    = 1024;                 // 3 stages
    constexpr int OFF_B    = 1024 + 3 * ASTG;      // 3 stages
    // total = 1024 + 3*18432 + 3*17408 = 108544 -> 2 CTAs/SM

    const uint32_t su = s2u(smem);
    const int cnt = g_count[e];
    const int rows = min(BM, cnt - m0);

    const int tid  = threadIdx.x;
    const int lane = tid & 31;
    const int warp = tid >> 5;
    const int gid  = lane >> 2;
    const int itg  = lane & 3;
    const int wm = warp >> 1;
    const int wn = warp & 1;

    int* sSlot = (int*)(smem + OFF_SLOT);
    sSlot[tid] = g_slots[e * N_TOK + m0 + ((tid < rows) ? tid : 0)];
    __syncthreads();

    const __half* Wb = (FIRST ? g_W1h : g_W2h)
                     + (size_t)e * (size_t)K * N + n0;   // [K][N], column block n0

    // quarter-stage: parts 0..3, each 4 cpa16/thread; commit at part 3.
    auto qstage = [&](int s, int part) {
        const int k0 = s * BK;
        const int sl = s % 3;
        const uint32_t ab = su + OFF_A + sl * ASTG;
        const uint32_t bb = su + OFF_B + sl * BSTG;
#pragma unroll
        for (int it = 2 * part; it < 2 * part + 2; it++) {   // A: 128 m-rows x 8 chunks
            int idx = it * 128 + tid;
            int row = idx >> 3, c = idx & 7;
            int slot = sSlot[row];
            const __half* g = FIRST
                ? g_Xh + (size_t)(slot >> 1) * D_IN  + k0 + c * 8
                : g_Hh + (size_t)slot        * D_HID + k0 + c * 8;
            cpa16(ab + row * STRA + c * 16, g);
        }
#pragma unroll
        for (int it = 2 * part; it < 2 * part + 2; it++) {   // B: 64 k-rows x 16 chunks
            int idx = it * 128 + tid;
            int row = idx >> 4, c = idx & 15;
            cpa16(bb + row * STRBN + c * 16,
                  Wb + (size_t)(k0 + row) * N + c * 8);
        }
        if (part == 3) asm volatile("cp.async.commit_group;\n");
    };
    auto stage = [&](int s) {
#pragma unroll
        for (int part = 0; part < 4; part++) qstage(s, part);
    };

    float acc[4][8][4];
#pragma unroll
    for (int a = 0; a < 4; a++)
#pragma unroll
        for (int b = 0; b < 8; b++)
#pragma unroll
            for (int c = 0; c < 4; c++) acc[a][b][c] = 0.f;

    const uint32_t aLane = (uint32_t)((wm * 64 + (lane & 15)) * STRA + (lane >> 4) * 16);
    // B trans lanes: kRow = lane&15, n-offset = (lane&16 ? 8 : 0)
    const uint32_t bLane = (uint32_t)((lane & 15) * STRBN
                                      + (wn * 64 + ((lane & 16) ? 8 : 0)) * 2);

    stage(0);
    stage(1);
    for (int s = 0; s < NS; ++s) {
        if (s + 1 < NS) {
            asm volatile("cp.async.wait_group 1;\n");
        } else {
            asm volatile("cp.async.wait_group 0;\n");
        }
        __syncthreads();

        const int sl = s % 3;
        const uint32_t aS = su + OFF_A + sl * ASTG + aLane;
        const uint32_t bS = su + OFF_B + sl * BSTG + bLane;

        uint32_t af[2][4][4], bf[2][4][4];
#pragma unroll
        for (int mf = 0; mf < 4; ++mf) LDSM_X4(af[0][mf], aS + mf * 16 * STRA);
#pragma unroll
        for (int p = 0; p < 4; ++p)    LDSM_X4T(bf[0][p], bS + p * 32);

#pragma unroll
        for (int ks = 0; ks < BK / 16; ++ks) {
            const int cur = ks & 1, nxt = cur ^ 1;
            if (ks + 1 < BK / 16) {
#pragma unroll
                for (int mf = 0; mf < 4; ++mf)
                    LDSM_X4(af[nxt][mf], aS + (ks + 1) * 32 + mf * 16 * STRA);
#pragma unroll
                for (int p = 0; p < 4; ++p)
                    LDSM_X4T(bf[nxt][p], bS + (ks + 1) * 16 * STRBN + p * 32);
            }
            if (s + 2 < NS) qstage(s + 2, ks);   // spread next-next-stage loads
#pragma unroll
            for (int mf = 0; mf < 4; ++mf)
#pragma unroll
                for (int p = 0; p < 4; ++p) {
                    mma_f16(acc[mf][2 * p],     af[cur][mf], &bf[cur][p][0]);
                    mma_f16(acc[mf][2 * p + 1], af[cur][mf], &bf[cur][p][2]);
                }
        }
    }

#pragma unroll
    for (int mf = 0; mf < 4; ++mf) {
        int rl = wm * 64 + mf * 16 + gid;
#pragma unroll
        for (int nf = 0; nf < 8; ++nf) {
            int n = n0 + wn * 64 + nf * 8 + 2 * itg;
            float2 bv = *(const float2*)(Bias + (size_t)e * N + n);
            float v00 = acc[mf][nf][0] + bv.x;
            float v01 = acc[mf][nf][1] + bv.y;
            float v10 = acc[mf][nf][2] + bv.x;
            float v11 = acc[mf][nf][3] + bv.y;
            if (FIRST) {
                v00 = fmaxf(v00, 0.f); v01 = fmaxf(v01, 0.f);
                v10 = fmaxf(v10, 0.f); v11 = fmaxf(v11, 0.f);
                if (rl < rows) {
                    int slot = sSlot[rl];
                    *(half2*)(g_Hh + (size_t)slot * D_HID + n) = __floats2half2_rn(v00, v01);
                }
                if (rl + 8 < rows) {
                    int slot = sSlot[rl + 8];
                    *(half2*)(g_Hh + (size_t)slot * D_HID + n) = __floats2half2_rn(v10, v11);
                }
            } else {
                if (rl < rows) {
                    int slot = sSlot[rl];
                    float w = g_topk_w[slot];
                    float* o = out + (size_t)(slot >> 1) * D_OUT + n;
                    redadd(o,     v00 * w);
                    redadd(o + 1, v01 * w);
                }
                if (rl + 8 < rows) {
                    int slot = sSlot[rl + 8];
                    float w = g_topk_w[slot];
                    float* o = out + (size_t)(slot >> 1) * D_OUT + n;
                    redadd(o,     v10 * w);
                    redadd(o + 1, v11 * w);
                }
            }
        }
    }
}

// ---------------- F1: ffn layer 1 + convert-W2 batches + out-zeroing ----------------
// bids [0,10240): 4 GEMM tiles : 1 convert batch (bid%5). bids [10240,12288): zero out.
__global__ void __launch_bounds__(128, 2)
f1_kernel(const float* __restrict__ b1, const float* __restrict__ W2,
          float* __restrict__ out) {
    extern __shared__ __align__(128) char smem[];
    const int bid = blockIdx.x;
    if (bid >= 10240) {                     // ---- zero out (consumed only by f2's red.add) ----
        const int z = bid - 10240;
        float4* o = (float4*)out + (size_t)z * 512 + threadIdx.x;
#pragma unroll
        for (int q = 0; q < 4; q++) o[q * 128] = make_float4(0.f, 0.f, 0.f, 0.f);
        return;
    }
    const int i = bid / 5, r = bid % 5;
    if (r < 4) {
        const int j = i * 4 + r;            // f1 GEMM tile in [0,8192)
        const int nt = j & 31, mt = (j >> 5) & 31, e = j >> 10;
        if (mt * 128 >= g_count[e]) return;
        ffn_body<true>(e, mt * 128, nt * 128, b1, nullptr, smem);
    } else {
        // convert W2 batch i in [0,2048): 4096 float4 (8M total)
        convert_block(W2, g_W2h, (size_t)i * 4096, 32, 128, threadIdx.x);
    }
}

// ---------------- F2: ffn layer 2 (+fused combine via red.add) ----------------
__global__ void __launch_bounds__(128, 2)
f2_kernel(const float* __restrict__ b2, float* __restrict__ out) {
    extern __shared__ __align__(128) char smem[];
    const int e = blockIdx.z, mt = blockIdx.y, nt = blockIdx.x;
    if (mt * 128 >= g_count[e]) return;
    ffn_body<false>(e, mt * 128, nt * 128, b2, out, smem);
}

// ---------------- launch ----------------
extern "C" void kernel_launch(void* const* d_in, const int* in_sizes, int n_in,
                              void* d_out, int out_size) {
    const float* x  = (const float*)d_in[0];
    const float* W1 = (const float*)d_in[1];
    const float* b1 = (const float*)d_in[2];
    const float* W2 = (const float*)d_in[3];
    const float* b2 = (const float*)d_in[4];
    const float* Wg = (const float*)d_in[5];
    const float* bg = (const float*)d_in[6];
    float* out = (float*)d_out;

    constexpr int SMEM_FFN = 1024 + 3 * (128 * 144) + 3 * (64 * 272);   // 108544 -> 2 CTAs/SM
    cudaFuncSetAttribute(f1_kernel, cudaFuncAttributeMaxDynamicSharedMemorySize, SMEM_FFN);
    cudaFuncSetAttribute(f2_kernel, cudaFuncAttributeMaxDynamicSharedMemorySize, SMEM_FFN);

    init0_kernel<<<1, 32>>>();
    prep_kernel<<<4608, 256>>>(x, W1, Wg, bg);       // 4096 convert-W1 + 512 gating
    f1_kernel<<<10240 + 2048, 128, SMEM_FFN>>>(b1, W2, out);
    f2_kernel<<<dim3(D_OUT / 128, N_TOK / 128, N_EXP), 128, SMEM_FFN>>>(b2, out);
}